// round 9
// baseline (speedup 1.0000x reference)
#include <cuda_runtime.h>
#include <cuda_fp16.h>

// ---------------- problem constants ----------------
#define NN    100000
#define EE    1600000
#define WIN   256
#define WH    64
#define NT    4
#define KHOP  10
#define ALPHAF 0.1f
#define MTOT  (NN*WH)          // 6,400,000
#define HB    (1<<18)          // histogram bins
#define HBLK  64               // loss blocks (HB/4096)
#define HRANGE 12.0f
#define NB1   1024             // stats partial blocks
#define ROWS_PER_SB 98
#define NSB   98               // ceil(100000/1024) for rowptr scan

// ---------------- device scratch (static, no allocation) ----------------
__device__ float4 g_T4 [MTOT/4];     // tilde_H fp32 (restart term)
__device__ float4 g_H4 [MTOT/4];     // encoded H fp32
__device__ uint4  g_TH [MTOT/8];     // tilde_H fp16 (hop-0 gather input)
__device__ uint4  g_ZHa[MTOT/8];     // fp16 diffusion ping
__device__ uint4  g_ZHb[MTOT/8];     // fp16 diffusion pong
__device__ float g_part[NB1*512];
__device__ float g_part2[32*512];
__device__ __align__(16) float g_mean[NT*WH];
__device__ __align__(16) float g_std [NT*WH];
__device__ __align__(16) float g_invs[NT*WH];
__device__ int   g_tcnt[NT];
__device__ int   g_cnt[NN];
__device__ int   g_rowptr[NN+1];
__device__ int   g_cursor[NN];
__device__ int   g_col[EE];
__device__ float g_coef[NN];
__device__ int   g_hist[HB];
__device__ int   g_bsum[HBLK], g_bsumex[HBLK];
__device__ long long g_babs[HBLK];
__device__ int   g_sb[128], g_sbex[128];
__device__ int   g_ctrMid, g_ctrScan, g_ctrLA, g_ctrLC;

// ---------------- f32x2 packed helpers ----------------
__device__ __forceinline__ unsigned long long pk2(float a, float b) {
    unsigned long long r;
    asm("mov.b64 %0, {%1,%2};" : "=l"(r) : "f"(a), "f"(b));
    return r;
}
__device__ __forceinline__ void upk2(unsigned long long v, float& a, float& b) {
    asm("mov.b64 {%0,%1}, %2;" : "=f"(a), "=f"(b) : "l"(v));
}
__device__ __forceinline__ void fma2(unsigned long long& d, unsigned long long a,
                                     unsigned long long b) {
    asm("fma.rn.f32x2 %0, %1, %2, %3;" : "=l"(d) : "l"(a), "l"(b), "l"(d));
}

// ---------------- reduction helpers ----------------
template<int BS>
__device__ __forceinline__ int blockScanInc(int v, int* sh) {
    int tid = threadIdx.x;
    sh[tid] = v; __syncthreads();
    #pragma unroll
    for (int off = 1; off < BS; off <<= 1) {
        int t = (tid >= off) ? sh[tid - off] : 0;
        __syncthreads();
        sh[tid] += t;
        __syncthreads();
    }
    return sh[tid];
}
template<int BS>
__device__ __forceinline__ int blockReduceInt(int v, int* sh) {
    int tid = threadIdx.x;
    sh[tid] = v; __syncthreads();
    #pragma unroll
    for (int off = BS/2; off > 0; off >>= 1) {
        if (tid < off) sh[tid] += sh[tid + off];
        __syncthreads();
    }
    return sh[0];
}
template<int BS>
__device__ __forceinline__ long long blockReduceLL(long long v, long long* sh) {
    int tid = threadIdx.x;
    sh[tid] = v; __syncthreads();
    #pragma unroll
    for (int off = BS/2; off > 0; off >>= 1) {
        if (tid < off) sh[tid] += sh[tid + off];
        __syncthreads();
    }
    return sh[0];
}

// ---------------- zero scratch + counters ----------------
__global__ void k_zero() {
    int i = blockIdx.x * blockDim.x + threadIdx.x;   // 128*512 = 65536 = HB/4
    ((uint4*)g_hist)[i] = make_uint4(0,0,0,0);
    if (i < NN/4) ((uint4*)g_cnt)[i] = make_uint4(0,0,0,0);
    if (i == 0) {
        g_tcnt[0]=0; g_tcnt[1]=0; g_tcnt[2]=0; g_tcnt[3]=0;
        g_ctrMid=0; g_ctrScan=0; g_ctrLA=0; g_ctrLC=0;
    }
}

// ---------------- encode: H = l2norm_rows(X @ W + b) -> g_H4 ----------------
__global__ void __launch_bounds__(256) k_encode(const float* __restrict__ X,
                                                const float* __restrict__ W,
                                                const float* __restrict__ bvec) {
    __shared__ unsigned long long Xd[64][64];  // 32 KB
    __shared__ float Ws[64][64];               // 16 KB
    int tid  = threadIdx.x;
    int lane = tid & 31, wgrp = tid >> 5;
    int colp = lane;
    int rowBase = blockIdx.x * 64;
    int lr = tid >> 4, lc = tid & 15;

    unsigned long long acc[8];
    #pragma unroll
    for (int j = 0; j < 8; j++) acc[j] = 0ull;

    for (int q = 0; q < 4; q++) {
        #pragma unroll
        for (int rr = 0; rr < 64; rr += 16) {
            int row = rowBase + lr + rr;
            float4 xv = make_float4(0.f, 0.f, 0.f, 0.f);
            if (row < NN)
                xv = *(const float4*)&X[(size_t)row * WIN + q * 64 + lc * 4];
            Xd[lr + rr][lc * 4 + 0] = pk2(xv.x, xv.x);
            Xd[lr + rr][lc * 4 + 1] = pk2(xv.y, xv.y);
            Xd[lr + rr][lc * 4 + 2] = pk2(xv.z, xv.z);
            Xd[lr + rr][lc * 4 + 3] = pk2(xv.w, xv.w);
        }
        #pragma unroll
        for (int rr = 0; rr < 64; rr += 16)
            *(float4*)&Ws[lr + rr][lc * 4] =
                *(const float4*)&W[(size_t)(q * 64 + lr + rr) * WH + lc * 4];
        __syncthreads();

        #pragma unroll 8
        for (int k = 0; k < 64; k += 2) {
            unsigned long long w0 = *(const unsigned long long*)&Ws[k][colp * 2];
            unsigned long long w1 = *(const unsigned long long*)&Ws[k + 1][colp * 2];
            #pragma unroll
            for (int j = 0; j < 8; j++) {
                ulonglong2 xx = *(const ulonglong2*)&Xd[wgrp * 8 + j][k];
                fma2(acc[j], xx.x, w0);
                fma2(acc[j], xx.y, w1);
            }
        }
        __syncthreads();
    }

    float bb0 = bvec[colp * 2], bb1 = bvec[colp * 2 + 1];
    float* H = (float*)g_H4;
    #pragma unroll
    for (int j = 0; j < 8; j++) {
        float v0, v1; upk2(acc[j], v0, v1);
        v0 += bb0; v1 += bb1;
        float ss = v0 * v0 + v1 * v1;
        #pragma unroll
        for (int o = 16; o > 0; o >>= 1) ss += __shfl_xor_sync(0xffffffffu, ss, o);
        float inv = 1.0f / fmaxf(sqrtf(ss), 1e-12f);
        int row = rowBase + wgrp * 8 + j;
        if (row < NN) {
            float2 out2; out2.x = v0 * inv; out2.y = v1 * inv;
            *(float2*)&H[(size_t)row * WH + colp * 2] = out2;
        }
    }
}

// ---------------- degree counts + per-type counts (merged) ----------------
__global__ void k_cnt(const int* __restrict__ edge, const int* __restrict__ type) {
    __shared__ int c[NT];
    if (threadIdx.x < NT) c[threadIdx.x] = 0;
    __syncthreads();
    int base = blockIdx.x * blockDim.x + threadIdx.x;
    int stride = gridDim.x * blockDim.x;
    for (int i = base; i < EE; i += stride) atomicAdd(&g_cnt[edge[EE + i]], 1);
    for (int i = base; i < NN; i += stride) atomicAdd(&c[type[i]], 1);
    __syncthreads();
    if (threadIdx.x < NT && c[threadIdx.x]) atomicAdd(&g_tcnt[threadIdx.x], c[threadIdx.x]);
}

// ---------------- per-type sum / sumsq partials (float4, deterministic) ------
__global__ void __launch_bounds__(256) k_stats_partial(const int* __restrict__ type) {
    int tx = threadIdx.x, ty = threadIdx.y;
    int r0 = blockIdx.x * ROWS_PER_SB;
    int rend = min(r0 + ROWS_PER_SB, NN);
    float4 s0 = make_float4(0,0,0,0), s1 = s0, s2 = s0, s3 = s0;
    float4 q0 = s0, q1 = s0, q2 = s0, q3 = s0;
    for (int r = r0 + ty; r < rend; r += 16) {
        float4 v = g_H4[r * 16 + tx];
        float4 v2; v2.x = v.x*v.x; v2.y = v.y*v.y; v2.z = v.z*v.z; v2.w = v.w*v.w;
        int t = type[r];
        if (t == 0) {
            s0.x += v.x; s0.y += v.y; s0.z += v.z; s0.w += v.w;
            q0.x += v2.x; q0.y += v2.y; q0.z += v2.z; q0.w += v2.w;
        } else if (t == 1) {
            s1.x += v.x; s1.y += v.y; s1.z += v.z; s1.w += v.w;
            q1.x += v2.x; q1.y += v2.y; q1.z += v2.z; q1.w += v2.w;
        } else if (t == 2) {
            s2.x += v.x; s2.y += v.y; s2.z += v.z; s2.w += v.w;
            q2.x += v2.x; q2.y += v2.y; q2.z += v2.z; q2.w += v2.w;
        } else {
            s3.x += v.x; s3.y += v.y; s3.z += v.z; s3.w += v.w;
            q3.x += v2.x; q3.y += v2.y; q3.z += v2.z; q3.w += v2.w;
        }
    }
    __shared__ float4 sh[16][8][16];   // 32 KB
    sh[ty][0][tx] = s0; sh[ty][1][tx] = s1; sh[ty][2][tx] = s2; sh[ty][3][tx] = s3;
    sh[ty][4][tx] = q0; sh[ty][5][tx] = q1; sh[ty][6][tx] = q2; sh[ty][7][tx] = q3;
    __syncthreads();
    if (ty < 8) {
        float4 tot = make_float4(0,0,0,0);
        #pragma unroll
        for (int y = 0; y < 16; y++) {
            float4 v = sh[y][ty][tx];
            tot.x += v.x; tot.y += v.y; tot.z += v.z; tot.w += v.w;
        }
        *(float4*)&g_part[blockIdx.x * 512 + ty * 64 + tx * 4] = tot;
    }
}

// stage 2: 32 blocks x 512; last block also finalizes mean/std
__global__ void k_stats_mid() {
    int o = threadIdx.x;          // 0..511
    int b = blockIdx.x;           // 0..31
    float s = 0.f;
    #pragma unroll 8
    for (int j = 0; j < 32; j++)
        s += g_part[(b * 32 + j) * 512 + o];
    g_part2[b * 512 + o] = s;
    __threadfence();
    __shared__ int lastFlag;
    if (o == 0) lastFlag = (atomicAdd(&g_ctrMid, 1) == 31);
    __syncthreads();
    if (lastFlag && o < 256) {
        float S = 0.f, Q = 0.f;
        #pragma unroll 8
        for (int j = 0; j < 32; j++) {
            S += g_part2[j * 512 + o];
            Q += g_part2[j * 512 + 256 + o];
        }
        float c = (float)g_tcnt[o >> 6];
        float mean = S / c;
        float std  = (Q - c * mean * mean) / sqrtf(fmaxf(c - 1.0f, 1.0f));
        g_mean[o] = mean;
        g_std[o]  = std;
        g_invs[o] = 1.0f / std;
    }
}

// ---------------- whiten (fp32 + fp16 copies) + both histograms ----------------
__global__ void k_tilde(const int* __restrict__ type, const float4* __restrict__ gs) {
    const float invh = (float)HB / (2.0f * HRANGE);
    int i = blockIdx.x * blockDim.x + threadIdx.x;   // over MTOT/4
    int row = i >> 4, f4 = i & 15;
    int t = type[row];
    float4 v = g_H4[i];
    float4 m = *(const float4*)&g_mean[t * WH + f4 * 4];
    float4 s = *(const float4*)&g_invs[t * WH + f4 * 4];
    float4 o;
    o.x = (v.x - m.x) * s.x;
    o.y = (v.y - m.y) * s.y;
    o.z = (v.z - m.z) * s.z;
    o.w = (v.w - m.w) * s.w;
    g_T4[i] = o;
    __half2 h01 = __floats2half2_rn(o.x, o.y);
    __half2 h23 = __floats2half2_rn(o.z, o.w);
    ((uint2*)g_TH)[i] = make_uint2(*(unsigned*)&h01, *(unsigned*)&h23);
    atomicAdd(&g_hist[min(max((int)((o.x + HRANGE) * invh), 0), HB - 1)], 1);
    atomicAdd(&g_hist[min(max((int)((o.y + HRANGE) * invh), 0), HB - 1)], 1);
    atomicAdd(&g_hist[min(max((int)((o.z + HRANGE) * invh), 0), HB - 1)], 1);
    atomicAdd(&g_hist[min(max((int)((o.w + HRANGE) * invh), 0), HB - 1)], 1);
    float4 g = gs[i];
    atomicAdd(&g_hist[min(max((int)((g.x + HRANGE) * invh), 0), HB - 1)], -1);
    atomicAdd(&g_hist[min(max((int)((g.y + HRANGE) * invh), 0), HB - 1)], -1);
    atomicAdd(&g_hist[min(max((int)((g.z + HRANGE) * invh), 0), HB - 1)], -1);
    atomicAdd(&g_hist[min(max((int)((g.w + HRANGE) * invh), 0), HB - 1)], -1);
}

// ---------------- rowptr scan: stage1 (+ stage2 in last block) ----------------
__global__ void k_scan1() {
    __shared__ int sh[1024];
    int i = blockIdx.x * 1024 + threadIdx.x;
    int v = (i < NN) ? g_cnt[i] : 0;
    int tot = blockReduceInt<1024>(v, sh);
    if (threadIdx.x == 0) g_sb[blockIdx.x] = tot;
    __threadfence();
    __shared__ int lastFlag;
    if (threadIdx.x == 0) lastFlag = (atomicAdd(&g_ctrScan, 1) == NSB - 1);
    __syncthreads();
    if (lastFlag) {
        int w = (threadIdx.x < NSB) ? g_sb[threadIdx.x] : 0;
        int incl = blockScanInc<1024>(w, sh);
        if (threadIdx.x < 128) g_sbex[threadIdx.x] = incl - w;
    }
}
__global__ void k_scan3() {
    __shared__ int sh[1024];
    int i = blockIdx.x * 1024 + threadIdx.x;
    int v = (i < NN) ? g_cnt[i] : 0;
    int incl = blockScanInc<1024>(v, sh);
    int total = g_sbex[blockIdx.x] + incl;
    if (i < NN) {
        g_rowptr[i + 1] = total;
        g_cursor[i]     = total - v;
        g_coef[i]       = (1.0f - ALPHAF) / fmaxf((float)v, 1.0f);
    }
    if (i == 0) g_rowptr[0] = 0;
}

// ---------------- CSR fill ----------------
__global__ void k_fill(const int* __restrict__ edge) {
    int i = blockIdx.x * blockDim.x + threadIdx.x;
    int stride = gridDim.x * blockDim.x;
    for (; i < EE; i += stride) {
        int src = edge[i];
        int dst = edge[EE + i];
        int p = atomicAdd(&g_cursor[dst], 1);
        g_col[p] = src;
    }
}

// ---------------- one PPR diffusion step, fp16 state, fp32 accumulate --------
// block (8,32): 32 rows/block, thread.x = uint4 chunk of 8 halves.
// 8-deep MLP main loop + scalar tail (R6-proven register footprint).
template<bool LAST>
__global__ void __launch_bounds__(256) k_diffuse(int it, const int* __restrict__ type,
                                                 float* __restrict__ out) {
    const uint4* Zin  = (it == 0) ? g_TH : ((it & 1) ? g_ZHa : g_ZHb);
    uint4*       Zout = (it & 1) ? g_ZHb : g_ZHa;
    int row = blockIdx.x * 32 + threadIdx.y;
    int f = threadIdx.x;   // 0..7
    int beg = g_rowptr[row], end = g_rowptr[row + 1];
    float a[8];
    #pragma unroll
    for (int j = 0; j < 8; j++) a[j] = 0.f;

    int e = beg;
    for (; e + 8 <= end; e += 8) {
        int c[8];
        #pragma unroll
        for (int u = 0; u < 8; u++) c[u] = g_col[e + u];
        uint4 v[8];
        #pragma unroll
        for (int u = 0; u < 8; u++) v[u] = Zin[c[u] * 8 + f];
        #pragma unroll
        for (int u = 0; u < 8; u++) {
            const __half2* h = (const __half2*)&v[u];
            #pragma unroll
            for (int p = 0; p < 4; p++) {
                float2 fv = __half22float2(h[p]);
                a[p * 2]     += fv.x;
                a[p * 2 + 1] += fv.y;
            }
        }
    }
    for (; e < end; e++) {
        uint4 v = Zin[g_col[e] * 8 + f];
        const __half2* h = (const __half2*)&v;
        #pragma unroll
        for (int p = 0; p < 4; p++) {
            float2 fv = __half22float2(h[p]);
            a[p * 2]     += fv.x;
            a[p * 2 + 1] += fv.y;
        }
    }

    float cf = g_coef[row];
    float4 t0 = g_T4[row * 16 + f * 2];
    float4 t1 = g_T4[row * 16 + f * 2 + 1];
    float o[8];
    o[0] = cf * a[0] + ALPHAF * t0.x;
    o[1] = cf * a[1] + ALPHAF * t0.y;
    o[2] = cf * a[2] + ALPHAF * t0.z;
    o[3] = cf * a[3] + ALPHAF * t0.w;
    o[4] = cf * a[4] + ALPHAF * t1.x;
    o[5] = cf * a[5] + ALPHAF * t1.y;
    o[6] = cf * a[6] + ALPHAF * t1.z;
    o[7] = cf * a[7] + ALPHAF * t1.w;

    if (!LAST) {
        __half2 h0 = __floats2half2_rn(o[0], o[1]);
        __half2 h1 = __floats2half2_rn(o[2], o[3]);
        __half2 h2 = __floats2half2_rn(o[4], o[5]);
        __half2 h3 = __floats2half2_rn(o[6], o[7]);
        uint4 pv;
        pv.x = *(unsigned*)&h0; pv.y = *(unsigned*)&h1;
        pv.z = *(unsigned*)&h2; pv.w = *(unsigned*)&h3;
        Zout[row * 8 + f] = pv;
    } else {
        int ty = type[row];
        float w[8];
        #pragma unroll
        for (int j = 0; j < 8; j++)
            w[j] = o[j] * g_std[ty * WH + f * 8 + j] + g_mean[ty * WH + f * 8 + j];
        float ss = 0.f;
        #pragma unroll
        for (int j = 0; j < 8; j++) ss += w[j] * w[j];
        #pragma unroll
        for (int off = 4; off > 0; off >>= 1) ss += __shfl_xor_sync(0xffffffffu, ss, off);
        float inv = 1.0f / fmaxf(sqrtf(ss), 1e-12f);
        float4 r0, r1;
        r0.x = w[0]*inv; r0.y = w[1]*inv; r0.z = w[2]*inv; r0.w = w[3]*inv;
        r1.x = w[4]*inv; r1.y = w[5]*inv; r1.z = w[6]*inv; r1.w = w[7]*inv;
        *(float4*)&out[(size_t)row * WH + f * 8]     = r0;
        *(float4*)&out[(size_t)row * WH + f * 8 + 4] = r1;
    }
}

// ---------------- W1 loss: Sum |prefix(hist)| * h / M ----------------
__global__ void k_lossA() {
    __shared__ int sh[1024];
    int base = blockIdx.x * 4096 + threadIdx.x * 4;
    int s = g_hist[base] + g_hist[base+1] + g_hist[base+2] + g_hist[base+3];
    int tot = blockReduceInt<1024>(s, sh);
    if (threadIdx.x == 0) g_bsum[blockIdx.x] = tot;
    __threadfence();
    __shared__ int lastFlag;
    if (threadIdx.x == 0) lastFlag = (atomicAdd(&g_ctrLA, 1) == HBLK - 1);
    __syncthreads();
    if (lastFlag) {
        int w = (threadIdx.x < HBLK) ? g_bsum[threadIdx.x] : 0;
        int incl = blockScanInc<1024>(w, sh);
        if (threadIdx.x < HBLK) g_bsumex[threadIdx.x] = incl - w;
    }
}
__global__ void k_lossC(float* __restrict__ out, int out_size) {
    __shared__ int shs[1024];
    __shared__ long long shl[1024];
    int base = blockIdx.x * 4096 + threadIdx.x * 4;
    int h0 = g_hist[base], h1 = g_hist[base+1], h2 = g_hist[base+2], h3 = g_hist[base+3];
    int s = h0 + h1 + h2 + h3;
    int incl = blockScanInc<1024>(s, shs);
    int off = g_bsumex[blockIdx.x] + incl - s;
    int p1 = off + h0;
    int p2 = p1 + h1;
    int p3 = p2 + h2;
    int p4 = p3 + h3;
    long long a = (long long)abs(p1) + abs(p2) + abs(p3) + abs(p4);
    long long tot = blockReduceLL<1024>(a, shl);
    if (threadIdx.x == 0) g_babs[blockIdx.x] = tot;
    __threadfence();
    __shared__ int lastFlag;
    if (threadIdx.x == 0) lastFlag = (atomicAdd(&g_ctrLC, 1) == HBLK - 1);
    __syncthreads();
    if (lastFlag) {
        long long v = (threadIdx.x < HBLK) ? g_babs[threadIdx.x] : 0ll;
        long long all = blockReduceLL<1024>(v, shl);
        if (threadIdx.x == 0 && out_size > MTOT) {
            double h = (2.0 * (double)HRANGE) / (double)HB;
            out[MTOT] = (float)((double)all * h / (double)MTOT);
        }
    }
}

// ---------------- launcher: DAG via stream fork/join (graph-capturable) ------
extern "C" void kernel_launch(void* const* d_in, const int* in_sizes, int n_in,
                              void* d_out, int out_size) {
    const float* X    = (const float*)d_in[0];
    const float* W    = (const float*)d_in[1];
    const float* bvec = (const float*)d_in[2];
    const float* gs   = (const float*)d_in[3];
    const int*   edge = (const int*)d_in[4];
    const int*   type = (const int*)d_in[5];
    float* out = (float*)d_out;

    cudaStream_t s1, s2;
    cudaStreamCreateWithFlags(&s1, cudaStreamNonBlocking);
    cudaStreamCreateWithFlags(&s2, cudaStreamNonBlocking);
    cudaEvent_t ev0, evC, ev1, evT, ev2;
    cudaEventCreateWithFlags(&ev0, cudaEventDisableTiming);
    cudaEventCreateWithFlags(&evC, cudaEventDisableTiming);
    cudaEventCreateWithFlags(&ev1, cudaEventDisableTiming);
    cudaEventCreateWithFlags(&evT, cudaEventDisableTiming);
    cudaEventCreateWithFlags(&ev2, cudaEventDisableTiming);

    // root
    k_zero<<<128, 512>>>();
    cudaEventRecord(ev0, 0);

    // edge chain on s1 (concurrent with feature chain)
    cudaStreamWaitEvent(s1, ev0, 0);
    k_cnt<<<2048, 256, 0, s1>>>(edge, type);
    cudaEventRecord(evC, s1);                         // g_tcnt ready
    k_scan1<<<NSB, 1024, 0, s1>>>();
    k_scan3<<<NSB, 1024, 0, s1>>>();
    k_fill<<<2048, 256, 0, s1>>>(edge);
    cudaEventRecord(ev1, s1);

    // feature chain on default stream
    k_encode<<<(NN + 63) / 64, 256>>>(X, W, bvec);
    k_stats_partial<<<NB1, dim3(16, 16)>>>(type);
    cudaStreamWaitEvent(0, evC, 0);                   // stats_mid reads g_tcnt
    k_stats_mid<<<32, 512>>>();
    k_tilde<<<MTOT / 4 / 256, 256>>>(type, (const float4*)gs);
    cudaEventRecord(evT, 0);

    // loss chain on s2, concurrent with diffusion
    cudaStreamWaitEvent(s2, evT, 0);
    k_lossA<<<HBLK, 1024, 0, s2>>>();
    k_lossC<<<HBLK, 1024, 0, s2>>>(out, out_size);
    cudaEventRecord(ev2, s2);

    // diffusion needs tilde (in-stream) + CSR (ev1)
    cudaStreamWaitEvent(0, ev1, 0);
    for (int it = 0; it < KHOP - 1; it++)
        k_diffuse<false><<<NN / 32, dim3(8, 32)>>>(it, type, out);
    k_diffuse<true><<<NN / 32, dim3(8, 32)>>>(KHOP - 1, type, out);

    // join loss chain back to origin stream
    cudaStreamWaitEvent(0, ev2, 0);

    cudaEventDestroy(ev0); cudaEventDestroy(evC); cudaEventDestroy(ev1);
    cudaEventDestroy(evT); cudaEventDestroy(ev2);
    cudaStreamDestroy(s1); cudaStreamDestroy(s2);
}

// round 10
// speedup vs baseline: 1.3375x; 1.3375x over previous
#include <cuda_runtime.h>
#include <cuda_fp16.h>

// ---------------- problem constants ----------------
#define NN    100000
#define EE    1600000
#define WIN   256
#define WH    64
#define NT    4
#define KHOP  10
#define ALPHAF 0.1f
#define MTOT  (NN*WH)          // 6,400,000
#define HB    (1<<20)          // histogram bins (contention knob! see R9 post-mortem)
#define HBLK  256              // loss blocks (HB/4096)
#define HRANGE 12.0f
#define NB1   1024             // stats partial blocks
#define ROWS_PER_SB 98
#define NSB   98               // ceil(100000/1024) for rowptr scan

// ---------------- device scratch (static, no allocation) ----------------
__device__ float4 g_T4 [MTOT/4];     // tilde_H fp32 (restart term)
__device__ float4 g_H4 [MTOT/4];     // encoded H fp32
__device__ uint4  g_TH [MTOT/8];     // tilde_H fp16 (hop-0 gather input + hist)
__device__ uint4  g_ZHa[MTOT/8];     // fp16 diffusion ping
__device__ uint4  g_ZHb[MTOT/8];     // fp16 diffusion pong
__device__ float g_part[NB1*512];
__device__ float g_part2[32*512];
__device__ __align__(16) float g_mean[NT*WH];
__device__ __align__(16) float g_std [NT*WH];
__device__ __align__(16) float g_invs[NT*WH];
__device__ int   g_tcnt[NT];
__device__ int   g_cnt[NN];
__device__ int   g_rowptr[NN+1];
__device__ int   g_cursor[NN];
__device__ int   g_col[EE];
__device__ float g_coef[NN];
__device__ int   g_hist[HB];
__device__ int   g_bsum[HBLK], g_bsumex[HBLK];
__device__ long long g_babs[HBLK];
__device__ int   g_sb[128], g_sbex[128];
__device__ int   g_ctrMid, g_ctrScan, g_ctrLA, g_ctrLC;

// ---------------- f32x2 packed helpers ----------------
__device__ __forceinline__ unsigned long long pk2(float a, float b) {
    unsigned long long r;
    asm("mov.b64 %0, {%1,%2};" : "=l"(r) : "f"(a), "f"(b));
    return r;
}
__device__ __forceinline__ void upk2(unsigned long long v, float& a, float& b) {
    asm("mov.b64 {%0,%1}, %2;" : "=f"(a), "=f"(b) : "l"(v));
}
__device__ __forceinline__ void fma2(unsigned long long& d, unsigned long long a,
                                     unsigned long long b) {
    asm("fma.rn.f32x2 %0, %1, %2, %3;" : "=l"(d) : "l"(a), "l"(b), "l"(d));
}

// ---------------- reduction helpers ----------------
template<int BS>
__device__ __forceinline__ int blockScanInc(int v, int* sh) {
    int tid = threadIdx.x;
    sh[tid] = v; __syncthreads();
    #pragma unroll
    for (int off = 1; off < BS; off <<= 1) {
        int t = (tid >= off) ? sh[tid - off] : 0;
        __syncthreads();
        sh[tid] += t;
        __syncthreads();
    }
    return sh[tid];
}
template<int BS>
__device__ __forceinline__ int blockReduceInt(int v, int* sh) {
    int tid = threadIdx.x;
    sh[tid] = v; __syncthreads();
    #pragma unroll
    for (int off = BS/2; off > 0; off >>= 1) {
        if (tid < off) sh[tid] += sh[tid + off];
        __syncthreads();
    }
    return sh[0];
}
template<int BS>
__device__ __forceinline__ long long blockReduceLL(long long v, long long* sh) {
    int tid = threadIdx.x;
    sh[tid] = v; __syncthreads();
    #pragma unroll
    for (int off = BS/2; off > 0; off >>= 1) {
        if (tid < off) sh[tid] += sh[tid + off];
        __syncthreads();
    }
    return sh[0];
}

// ---------------- zero scratch + counters ----------------
__global__ void k_zero() {
    int i = blockIdx.x * blockDim.x + threadIdx.x;   // 512*512 = 262144 = HB/4
    ((uint4*)g_hist)[i] = make_uint4(0,0,0,0);
    if (i < NN/4) ((uint4*)g_cnt)[i] = make_uint4(0,0,0,0);
    if (i == 0) {
        g_tcnt[0]=0; g_tcnt[1]=0; g_tcnt[2]=0; g_tcnt[3]=0;
        g_ctrMid=0; g_ctrScan=0; g_ctrLA=0; g_ctrLC=0;
    }
}

// ---------------- encode: H = l2norm_rows(X @ W + b) -> g_H4 ----------------
__global__ void __launch_bounds__(256) k_encode(const float* __restrict__ X,
                                                const float* __restrict__ W,
                                                const float* __restrict__ bvec) {
    __shared__ unsigned long long Xd[64][64];  // 32 KB
    __shared__ float Ws[64][64];               // 16 KB
    int tid  = threadIdx.x;
    int lane = tid & 31, wgrp = tid >> 5;
    int colp = lane;
    int rowBase = blockIdx.x * 64;
    int lr = tid >> 4, lc = tid & 15;

    unsigned long long acc[8];
    #pragma unroll
    for (int j = 0; j < 8; j++) acc[j] = 0ull;

    for (int q = 0; q < 4; q++) {
        #pragma unroll
        for (int rr = 0; rr < 64; rr += 16) {
            int row = rowBase + lr + rr;
            float4 xv = make_float4(0.f, 0.f, 0.f, 0.f);
            if (row < NN)
                xv = *(const float4*)&X[(size_t)row * WIN + q * 64 + lc * 4];
            Xd[lr + rr][lc * 4 + 0] = pk2(xv.x, xv.x);
            Xd[lr + rr][lc * 4 + 1] = pk2(xv.y, xv.y);
            Xd[lr + rr][lc * 4 + 2] = pk2(xv.z, xv.z);
            Xd[lr + rr][lc * 4 + 3] = pk2(xv.w, xv.w);
        }
        #pragma unroll
        for (int rr = 0; rr < 64; rr += 16)
            *(float4*)&Ws[lr + rr][lc * 4] =
                *(const float4*)&W[(size_t)(q * 64 + lr + rr) * WH + lc * 4];
        __syncthreads();

        #pragma unroll 8
        for (int k = 0; k < 64; k += 2) {
            unsigned long long w0 = *(const unsigned long long*)&Ws[k][colp * 2];
            unsigned long long w1 = *(const unsigned long long*)&Ws[k + 1][colp * 2];
            #pragma unroll
            for (int j = 0; j < 8; j++) {
                ulonglong2 xx = *(const ulonglong2*)&Xd[wgrp * 8 + j][k];
                fma2(acc[j], xx.x, w0);
                fma2(acc[j], xx.y, w1);
            }
        }
        __syncthreads();
    }

    float bb0 = bvec[colp * 2], bb1 = bvec[colp * 2 + 1];
    float* H = (float*)g_H4;
    #pragma unroll
    for (int j = 0; j < 8; j++) {
        float v0, v1; upk2(acc[j], v0, v1);
        v0 += bb0; v1 += bb1;
        float ss = v0 * v0 + v1 * v1;
        #pragma unroll
        for (int o = 16; o > 0; o >>= 1) ss += __shfl_xor_sync(0xffffffffu, ss, o);
        float inv = 1.0f / fmaxf(sqrtf(ss), 1e-12f);
        int row = rowBase + wgrp * 8 + j;
        if (row < NN) {
            float2 out2; out2.x = v0 * inv; out2.y = v1 * inv;
            *(float2*)&H[(size_t)row * WH + colp * 2] = out2;
        }
    }
}

// ---------------- degree counts + per-type counts (merged) ----------------
__global__ void k_cnt(const int* __restrict__ edge, const int* __restrict__ type) {
    __shared__ int c[NT];
    if (threadIdx.x < NT) c[threadIdx.x] = 0;
    __syncthreads();
    int base = blockIdx.x * blockDim.x + threadIdx.x;
    int stride = gridDim.x * blockDim.x;
    for (int i = base; i < EE; i += stride) atomicAdd(&g_cnt[edge[EE + i]], 1);
    for (int i = base; i < NN; i += stride) atomicAdd(&c[type[i]], 1);
    __syncthreads();
    if (threadIdx.x < NT && c[threadIdx.x]) atomicAdd(&g_tcnt[threadIdx.x], c[threadIdx.x]);
}

// ---------------- per-type sum / sumsq partials (float4, deterministic) ------
__global__ void __launch_bounds__(256) k_stats_partial(const int* __restrict__ type) {
    int tx = threadIdx.x, ty = threadIdx.y;
    int r0 = blockIdx.x * ROWS_PER_SB;
    int rend = min(r0 + ROWS_PER_SB, NN);
    float4 s0 = make_float4(0,0,0,0), s1 = s0, s2 = s0, s3 = s0;
    float4 q0 = s0, q1 = s0, q2 = s0, q3 = s0;
    for (int r = r0 + ty; r < rend; r += 16) {
        float4 v = g_H4[r * 16 + tx];
        float4 v2; v2.x = v.x*v.x; v2.y = v.y*v.y; v2.z = v.z*v.z; v2.w = v.w*v.w;
        int t = type[r];
        if (t == 0) {
            s0.x += v.x; s0.y += v.y; s0.z += v.z; s0.w += v.w;
            q0.x += v2.x; q0.y += v2.y; q0.z += v2.z; q0.w += v2.w;
        } else if (t == 1) {
            s1.x += v.x; s1.y += v.y; s1.z += v.z; s1.w += v.w;
            q1.x += v2.x; q1.y += v2.y; q1.z += v2.z; q1.w += v2.w;
        } else if (t == 2) {
            s2.x += v.x; s2.y += v.y; s2.z += v.z; s2.w += v.w;
            q2.x += v2.x; q2.y += v2.y; q2.z += v2.z; q2.w += v2.w;
        } else {
            s3.x += v.x; s3.y += v.y; s3.z += v.z; s3.w += v.w;
            q3.x += v2.x; q3.y += v2.y; q3.z += v2.z; q3.w += v2.w;
        }
    }
    __shared__ float4 sh[16][8][16];   // 32 KB
    sh[ty][0][tx] = s0; sh[ty][1][tx] = s1; sh[ty][2][tx] = s2; sh[ty][3][tx] = s3;
    sh[ty][4][tx] = q0; sh[ty][5][tx] = q1; sh[ty][6][tx] = q2; sh[ty][7][tx] = q3;
    __syncthreads();
    if (ty < 8) {
        float4 tot = make_float4(0,0,0,0);
        #pragma unroll
        for (int y = 0; y < 16; y++) {
            float4 v = sh[y][ty][tx];
            tot.x += v.x; tot.y += v.y; tot.z += v.z; tot.w += v.w;
        }
        *(float4*)&g_part[blockIdx.x * 512 + ty * 64 + tx * 4] = tot;
    }
}

// stage 2: 32 blocks x 512; last block also finalizes mean/std
__global__ void k_stats_mid() {
    int o = threadIdx.x;          // 0..511
    int b = blockIdx.x;           // 0..31
    float s = 0.f;
    #pragma unroll 8
    for (int j = 0; j < 32; j++)
        s += g_part[(b * 32 + j) * 512 + o];
    g_part2[b * 512 + o] = s;
    __threadfence();
    __shared__ int lastFlag;
    if (o == 0) lastFlag = (atomicAdd(&g_ctrMid, 1) == 31);
    __syncthreads();
    if (lastFlag && o < 256) {
        float S = 0.f, Q = 0.f;
        #pragma unroll 8
        for (int j = 0; j < 32; j++) {
            S += g_part2[j * 512 + o];
            Q += g_part2[j * 512 + 256 + o];
        }
        float c = (float)g_tcnt[o >> 6];
        float mean = S / c;
        float std  = (Q - c * mean * mean) / sqrtf(fmaxf(c - 1.0f, 1.0f));
        g_mean[o] = mean;
        g_std[o]  = std;
        g_invs[o] = 1.0f / std;
    }
}

// ---------------- whiten only (fp32 + fp16 copies); hist moved off-path -------
__global__ void k_tilde(const int* __restrict__ type) {
    int i = blockIdx.x * blockDim.x + threadIdx.x;   // over MTOT/4
    int row = i >> 4, f4 = i & 15;
    int t = type[row];
    float4 v = g_H4[i];
    float4 m = *(const float4*)&g_mean[t * WH + f4 * 4];
    float4 s = *(const float4*)&g_invs[t * WH + f4 * 4];
    float4 o;
    o.x = (v.x - m.x) * s.x;
    o.y = (v.y - m.y) * s.y;
    o.z = (v.z - m.z) * s.z;
    o.w = (v.w - m.w) * s.w;
    g_T4[i] = o;
    __half2 h01 = __floats2half2_rn(o.x, o.y);
    __half2 h23 = __floats2half2_rn(o.z, o.w);
    ((uint2*)g_TH)[i] = make_uint2(*(unsigned*)&h01, *(unsigned*)&h23);
}

// ---------------- histograms (runs on loss stream, concurrent with diffusion) -
__global__ void k_hist(const float4* __restrict__ gs) {
    const float invh = (float)HB / (2.0f * HRANGE);
    int i = blockIdx.x * blockDim.x + threadIdx.x;   // over MTOT/4
    uint2 hv = ((const uint2*)g_TH)[i];
    __half2 h01 = *(__half2*)&hv.x;
    __half2 h23 = *(__half2*)&hv.y;
    float2 e01 = __half22float2(h01);
    float2 e23 = __half22float2(h23);
    atomicAdd(&g_hist[min(max((int)((e01.x + HRANGE) * invh), 0), HB - 1)], 1);
    atomicAdd(&g_hist[min(max((int)((e01.y + HRANGE) * invh), 0), HB - 1)], 1);
    atomicAdd(&g_hist[min(max((int)((e23.x + HRANGE) * invh), 0), HB - 1)], 1);
    atomicAdd(&g_hist[min(max((int)((e23.y + HRANGE) * invh), 0), HB - 1)], 1);
    float4 g = gs[i];
    atomicAdd(&g_hist[min(max((int)((g.x + HRANGE) * invh), 0), HB - 1)], -1);
    atomicAdd(&g_hist[min(max((int)((g.y + HRANGE) * invh), 0), HB - 1)], -1);
    atomicAdd(&g_hist[min(max((int)((g.z + HRANGE) * invh), 0), HB - 1)], -1);
    atomicAdd(&g_hist[min(max((int)((g.w + HRANGE) * invh), 0), HB - 1)], -1);
}

// ---------------- rowptr scan: stage1 (+ stage2 in last block) ----------------
__global__ void k_scan1() {
    __shared__ int sh[1024];
    int i = blockIdx.x * 1024 + threadIdx.x;
    int v = (i < NN) ? g_cnt[i] : 0;
    int tot = blockReduceInt<1024>(v, sh);
    if (threadIdx.x == 0) g_sb[blockIdx.x] = tot;
    __threadfence();
    __shared__ int lastFlag;
    if (threadIdx.x == 0) lastFlag = (atomicAdd(&g_ctrScan, 1) == NSB - 1);
    __syncthreads();
    if (lastFlag) {
        int w = (threadIdx.x < NSB) ? g_sb[threadIdx.x] : 0;
        int incl = blockScanInc<1024>(w, sh);
        if (threadIdx.x < 128) g_sbex[threadIdx.x] = incl - w;
    }
}
__global__ void k_scan3() {
    __shared__ int sh[1024];
    int i = blockIdx.x * 1024 + threadIdx.x;
    int v = (i < NN) ? g_cnt[i] : 0;
    int incl = blockScanInc<1024>(v, sh);
    int total = g_sbex[blockIdx.x] + incl;
    if (i < NN) {
        g_rowptr[i + 1] = total;
        g_cursor[i]     = total - v;
        g_coef[i]       = (1.0f - ALPHAF) / fmaxf((float)v, 1.0f);
    }
    if (i == 0) g_rowptr[0] = 0;
}

// ---------------- CSR fill ----------------
__global__ void k_fill(const int* __restrict__ edge) {
    int i = blockIdx.x * blockDim.x + threadIdx.x;
    int stride = gridDim.x * blockDim.x;
    for (; i < EE; i += stride) {
        int src = edge[i];
        int dst = edge[EE + i];
        int p = atomicAdd(&g_cursor[dst], 1);
        g_col[p] = src;
    }
}

// ---------------- one PPR diffusion step, fp16 state, fp32 accumulate --------
// block (8,32): 32 rows/block, thread.x = uint4 chunk of 8 halves.
// 8-deep MLP main loop + scalar tail (R6-proven register footprint).
template<bool LAST>
__global__ void __launch_bounds__(256) k_diffuse(int it, const int* __restrict__ type,
                                                 float* __restrict__ out) {
    const uint4* Zin  = (it == 0) ? g_TH : ((it & 1) ? g_ZHa : g_ZHb);
    uint4*       Zout = (it & 1) ? g_ZHb : g_ZHa;
    int row = blockIdx.x * 32 + threadIdx.y;
    int f = threadIdx.x;   // 0..7
    int beg = g_rowptr[row], end = g_rowptr[row + 1];
    float a[8];
    #pragma unroll
    for (int j = 0; j < 8; j++) a[j] = 0.f;

    int e = beg;
    for (; e + 8 <= end; e += 8) {
        int c[8];
        #pragma unroll
        for (int u = 0; u < 8; u++) c[u] = g_col[e + u];
        uint4 v[8];
        #pragma unroll
        for (int u = 0; u < 8; u++) v[u] = Zin[c[u] * 8 + f];
        #pragma unroll
        for (int u = 0; u < 8; u++) {
            const __half2* h = (const __half2*)&v[u];
            #pragma unroll
            for (int p = 0; p < 4; p++) {
                float2 fv = __half22float2(h[p]);
                a[p * 2]     += fv.x;
                a[p * 2 + 1] += fv.y;
            }
        }
    }
    for (; e < end; e++) {
        uint4 v = Zin[g_col[e] * 8 + f];
        const __half2* h = (const __half2*)&v;
        #pragma unroll
        for (int p = 0; p < 4; p++) {
            float2 fv = __half22float2(h[p]);
            a[p * 2]     += fv.x;
            a[p * 2 + 1] += fv.y;
        }
    }

    float cf = g_coef[row];
    float4 t0 = g_T4[row * 16 + f * 2];
    float4 t1 = g_T4[row * 16 + f * 2 + 1];
    float o[8];
    o[0] = cf * a[0] + ALPHAF * t0.x;
    o[1] = cf * a[1] + ALPHAF * t0.y;
    o[2] = cf * a[2] + ALPHAF * t0.z;
    o[3] = cf * a[3] + ALPHAF * t0.w;
    o[4] = cf * a[4] + ALPHAF * t1.x;
    o[5] = cf * a[5] + ALPHAF * t1.y;
    o[6] = cf * a[6] + ALPHAF * t1.z;
    o[7] = cf * a[7] + ALPHAF * t1.w;

    if (!LAST) {
        __half2 h0 = __floats2half2_rn(o[0], o[1]);
        __half2 h1 = __floats2half2_rn(o[2], o[3]);
        __half2 h2 = __floats2half2_rn(o[4], o[5]);
        __half2 h3 = __floats2half2_rn(o[6], o[7]);
        uint4 pv;
        pv.x = *(unsigned*)&h0; pv.y = *(unsigned*)&h1;
        pv.z = *(unsigned*)&h2; pv.w = *(unsigned*)&h3;
        Zout[row * 8 + f] = pv;
    } else {
        int ty = type[row];
        float w[8];
        #pragma unroll
        for (int j = 0; j < 8; j++)
            w[j] = o[j] * g_std[ty * WH + f * 8 + j] + g_mean[ty * WH + f * 8 + j];
        float ss = 0.f;
        #pragma unroll
        for (int j = 0; j < 8; j++) ss += w[j] * w[j];
        #pragma unroll
        for (int off = 4; off > 0; off >>= 1) ss += __shfl_xor_sync(0xffffffffu, ss, off);
        float inv = 1.0f / fmaxf(sqrtf(ss), 1e-12f);
        float4 r0, r1;
        r0.x = w[0]*inv; r0.y = w[1]*inv; r0.z = w[2]*inv; r0.w = w[3]*inv;
        r1.x = w[4]*inv; r1.y = w[5]*inv; r1.z = w[6]*inv; r1.w = w[7]*inv;
        *(float4*)&out[(size_t)row * WH + f * 8]     = r0;
        *(float4*)&out[(size_t)row * WH + f * 8 + 4] = r1;
    }
}

// ---------------- W1 loss: Sum |prefix(hist)| * h / M ----------------
__global__ void k_lossA() {
    __shared__ int sh[1024];
    int base = blockIdx.x * 4096 + threadIdx.x * 4;
    int s = g_hist[base] + g_hist[base+1] + g_hist[base+2] + g_hist[base+3];
    int tot = blockReduceInt<1024>(s, sh);
    if (threadIdx.x == 0) g_bsum[blockIdx.x] = tot;
    __threadfence();
    __shared__ int lastFlag;
    if (threadIdx.x == 0) lastFlag = (atomicAdd(&g_ctrLA, 1) == HBLK - 1);
    __syncthreads();
    if (lastFlag) {
        int w = (threadIdx.x < HBLK) ? g_bsum[threadIdx.x] : 0;
        int incl = blockScanInc<1024>(w, sh);
        if (threadIdx.x < HBLK) g_bsumex[threadIdx.x] = incl - w;
    }
}
__global__ void k_lossC(float* __restrict__ out, int out_size) {
    __shared__ int shs[1024];
    __shared__ long long shl[1024];
    int base = blockIdx.x * 4096 + threadIdx.x * 4;
    int h0 = g_hist[base], h1 = g_hist[base+1], h2 = g_hist[base+2], h3 = g_hist[base+3];
    int s = h0 + h1 + h2 + h3;
    int incl = blockScanInc<1024>(s, shs);
    int off = g_bsumex[blockIdx.x] + incl - s;
    int p1 = off + h0;
    int p2 = p1 + h1;
    int p3 = p2 + h2;
    int p4 = p3 + h3;
    long long a = (long long)abs(p1) + abs(p2) + abs(p3) + abs(p4);
    long long tot = blockReduceLL<1024>(a, shl);
    if (threadIdx.x == 0) g_babs[blockIdx.x] = tot;
    __threadfence();
    __shared__ int lastFlag;
    if (threadIdx.x == 0) lastFlag = (atomicAdd(&g_ctrLC, 1) == HBLK - 1);
    __syncthreads();
    if (lastFlag) {
        long long v = (threadIdx.x < HBLK) ? g_babs[threadIdx.x] : 0ll;
        long long all = blockReduceLL<1024>(v, shl);
        if (threadIdx.x == 0 && out_size > MTOT) {
            double h = (2.0 * (double)HRANGE) / (double)HB;
            out[MTOT] = (float)((double)all * h / (double)MTOT);
        }
    }
}

// ---------------- launcher: DAG via stream fork/join (graph-capturable) ------
extern "C" void kernel_launch(void* const* d_in, const int* in_sizes, int n_in,
                              void* d_out, int out_size) {
    const float* X    = (const float*)d_in[0];
    const float* W    = (const float*)d_in[1];
    const float* bvec = (const float*)d_in[2];
    const float* gs   = (const float*)d_in[3];
    const int*   edge = (const int*)d_in[4];
    const int*   type = (const int*)d_in[5];
    float* out = (float*)d_out;

    cudaStream_t s1, s2;
    cudaStreamCreateWithFlags(&s1, cudaStreamNonBlocking);
    cudaStreamCreateWithFlags(&s2, cudaStreamNonBlocking);
    cudaEvent_t ev0, evC, ev1, evT, ev2;
    cudaEventCreateWithFlags(&ev0, cudaEventDisableTiming);
    cudaEventCreateWithFlags(&evC, cudaEventDisableTiming);
    cudaEventCreateWithFlags(&ev1, cudaEventDisableTiming);
    cudaEventCreateWithFlags(&evT, cudaEventDisableTiming);
    cudaEventCreateWithFlags(&ev2, cudaEventDisableTiming);

    // root
    k_zero<<<512, 512>>>();
    cudaEventRecord(ev0, 0);

    // edge chain on s1 (concurrent with feature chain)
    cudaStreamWaitEvent(s1, ev0, 0);
    k_cnt<<<2048, 256, 0, s1>>>(edge, type);
    cudaEventRecord(evC, s1);                         // g_tcnt ready
    k_scan1<<<NSB, 1024, 0, s1>>>();
    k_scan3<<<NSB, 1024, 0, s1>>>();
    k_fill<<<2048, 256, 0, s1>>>(edge);
    cudaEventRecord(ev1, s1);

    // feature chain on default stream
    k_encode<<<(NN + 63) / 64, 256>>>(X, W, bvec);
    k_stats_partial<<<NB1, dim3(16, 16)>>>(type);
    cudaStreamWaitEvent(0, evC, 0);                   // stats_mid reads g_tcnt
    k_stats_mid<<<32, 512>>>();
    k_tilde<<<MTOT / 4 / 256, 256>>>(type);
    cudaEventRecord(evT, 0);

    // loss chain on s2 (hist + prefix), concurrent with diffusion
    cudaStreamWaitEvent(s2, evT, 0);
    k_hist<<<MTOT / 4 / 256, 256, 0, s2>>>((const float4*)gs);
    k_lossA<<<HBLK, 1024, 0, s2>>>();
    k_lossC<<<HBLK, 1024, 0, s2>>>(out, out_size);
    cudaEventRecord(ev2, s2);

    // diffusion needs tilde (in-stream) + CSR (ev1)
    cudaStreamWaitEvent(0, ev1, 0);
    for (int it = 0; it < KHOP - 1; it++)
        k_diffuse<false><<<NN / 32, dim3(8, 32)>>>(it, type, out);
    k_diffuse<true><<<NN / 32, dim3(8, 32)>>>(KHOP - 1, type, out);

    // join loss chain back to origin stream
    cudaStreamWaitEvent(0, ev2, 0);

    cudaEventDestroy(ev0); cudaEventDestroy(evC); cudaEventDestroy(ev1);
    cudaEventDestroy(evT); cudaEventDestroy(ev2);
    cudaStreamDestroy(s1); cudaStreamDestroy(s2);
}